// round 10
// baseline (speedup 1.0000x reference)
#include <cuda_runtime.h>
#include <cstdint>

// Problem constants
#define C_DIM   64
#define HW      4096             // 64*64
#define N_PTS   131072           // B*H*W = 32*4096
#define K_CODES 1024
#define O_ELEMS 8388608          // B*C*H*W = 2^23
#define OFF_LOSS O_ELEMS
#define OFF_IDX  (O_ELEMS + 1)
#define NPART   (N_PTS / 32)     // 4096 warp partials

// Argmin tiling: 128 points x 64 codes per tile, 128 threads, 8x8 microtile
#define BM 128
#define BK 64
#define TH 128
#define NKT (K_CODES / BK)       // 16
#define ARG_SMEM (2 * 64 * 128 * 4)   // zs 32KB + ed 32KB = 64KB dynamic

// Scratch (device globals: allocation-free)
__device__ __align__(16) float g_enorm[K_CODES];   // ||e_k||^2
__device__ __align__(16) float g_znorm[N_PTS];     // ||z_n||^2
__device__ int   g_idx[N_PTS];
__device__ float g_partial[NPART];

// ---------------------------------------------------------------------------
// Warp tree sum of 64 squares (kept bit-identical to the R8 passing version)
// ---------------------------------------------------------------------------
__device__ __forceinline__ float warp_tree_sumsq(float a, float b) {
    float s = __fadd_rn(__fmul_rn(a, a), __fmul_rn(b, b));
    #pragma unroll
    for (int off = 16; off > 0; off >>= 1)
        s = __fadd_rn(s, __shfl_down_sync(0xffffffffu, s, off));
    return s;
}

__global__ void enorm_kernel(const float* __restrict__ emb) {
    int w = (blockIdx.x * blockDim.x + threadIdx.x) >> 5;
    int t = threadIdx.x & 31;
    if (w < K_CODES) {
        const float* r = emb + (size_t)w * C_DIM;
        float s = warp_tree_sumsq(r[t], r[t + 32]);
        if (t == 0) g_enorm[w] = s;
    }
}

__global__ void znorm_kernel(const float* __restrict__ x) {
    __shared__ float tile[C_DIM * 33];
    const int p0  = blockIdx.x * 32;
    const int b   = p0 >> 12;
    const int hw0 = p0 & 4095;
    const float* xb = x + (size_t)b * C_DIM * HW + hw0;
    const int lane = threadIdx.x & 31, wid = threadIdx.x >> 5;

    for (int c = wid; c < C_DIM; c += 8)
        tile[c * 33 + lane] = xb[(size_t)c * HW + lane];
    __syncthreads();

    #pragma unroll
    for (int q = 0; q < 4; q++) {
        int p = wid * 4 + q;
        float s = warp_tree_sumsq(tile[lane * 33 + p], tile[(lane + 32) * 33 + p]);
        if (lane == 0) g_znorm[p0 + p] = s;
    }
}

// ---------------------------------------------------------------------------
// Argmin: pairs packed along the POINT axis -> z pairs native from LDS.128,
// codebook stored duplicated {e,e} in smem (chunk-interleaved, conflict-free).
// Zero mov.b64 feeders in the mainloop. Per-lane dot = same sequential FMA
// chain over c as the validated R8 kernel -> identical indices.
// ---------------------------------------------------------------------------
extern __shared__ float smem_dyn[];

__global__ __launch_bounds__(TH, 3)
void argmin_kernel(const float* __restrict__ x, const float* __restrict__ emb) {
    float* zs = smem_dyn;            // [c][128] points
    float* ed = smem_dyn + 8192;     // [c][128] codes duplicated {e,e}
    float* red_val = zs;             // aliased after mainloop
    int*   red_idx = reinterpret_cast<int*>(zs + 1024);

    const int tid = threadIdx.x;
    const int P0  = blockIdx.x * BM;
    const int b   = P0 >> 12;
    const int hw0 = P0 & 4095;
    const float* xbase = x + (size_t)b * C_DIM * HW + hw0;

    // load z tile: zs[c][m]
    {
        int lane = tid & 31, w = tid >> 5;
        for (int c = w; c < C_DIM; c += 4) {
            float4 v = *reinterpret_cast<const float4*>(xbase + (size_t)c * HW + lane * 4);
            *reinterpret_cast<float4*>(zs + c * BM + lane * 4) = v;
        }
    }

    const int tck = tid & 7, tr = tid >> 3;   // 8 code-chunks x 16 point-rows
    const int m0 = tr * 8;

    // e-tile prefetch lane: 2 threads per code row, 32 channels each
    const int kk = tid >> 1, half = (tid & 1) * 32;

    // prefetch tile 0 into registers
    float4 r[8];
    {
        const float4* erow = reinterpret_cast<const float4*>(
            emb + (size_t)kk * C_DIM + half);
        #pragma unroll
        for (int i = 0; i < 8; i++) r[i] = __ldg(erow + i);
    }

    float4 znA = *reinterpret_cast<const float4*>(g_znorm + P0 + m0);
    float4 znB = *reinterpret_cast<const float4*>(g_znorm + P0 + m0 + 4);
    float zn[8] = { znA.x, znA.y, znA.z, znA.w, znB.x, znB.y, znB.z, znB.w };

    float minval[8];
    int   minidx[8];
    #pragma unroll
    for (int i = 0; i < 8; i++) { minval[i] = 3.0e38f; minidx[i] = 0; }

    for (int kt = 0; kt < NKT; kt++) {
        __syncthreads();   // previous readers done (covers zs writes on kt=0)
        // store prefetched tile duplicated: ed[c][2k] = ed[c][2k+1] = e_k[c]
        #pragma unroll
        for (int i = 0; i < 8; i++) {
            float4 v = r[i];
            int c = half + i * 4;
            *reinterpret_cast<float2*>(ed + (c + 0) * 128 + 2 * kk) = make_float2(v.x, v.x);
            *reinterpret_cast<float2*>(ed + (c + 1) * 128 + 2 * kk) = make_float2(v.y, v.y);
            *reinterpret_cast<float2*>(ed + (c + 2) * 128 + 2 * kk) = make_float2(v.z, v.z);
            *reinterpret_cast<float2*>(ed + (c + 3) * 128 + 2 * kk) = make_float2(v.w, v.w);
        }
        __syncthreads();

        // prefetch next tile (completes during mainloop)
        if (kt + 1 < NKT) {
            const float4* erow = reinterpret_cast<const float4*>(
                emb + (size_t)((kt + 1) * BK + kk) * C_DIM + half);
            #pragma unroll
            for (int i = 0; i < 8; i++) r[i] = __ldg(erow + i);
        }

        // acc[q][s][p]: chunk q (0..3), code-slot s (0..1), point-pair p (0..3)
        unsigned long long acc[4][2][4];
        #pragma unroll
        for (int q = 0; q < 4; q++)
            #pragma unroll
            for (int s = 0; s < 2; s++)
                #pragma unroll
                for (int p = 0; p < 4; p++) acc[q][s][p] = 0ull;

        #pragma unroll 2
        for (int c = 0; c < C_DIM; c++) {
            // z pairs: native consecutive points
            ulonglong2 zA = *reinterpret_cast<const ulonglong2*>(zs + c * BM + m0);
            ulonglong2 zB = *reinterpret_cast<const ulonglong2*>(zs + c * BM + m0 + 4);
            unsigned long long zp[4] = { zA.x, zA.y, zB.x, zB.y };
            #pragma unroll
            for (int q = 0; q < 4; q++) {
                // duplicated code pair-of-pairs: {e_a,e_a},{e_b,e_b}
                ulonglong2 e = *reinterpret_cast<const ulonglong2*>(
                    ed + c * 128 + 4 * (tck + 8 * q));
                #pragma unroll
                for (int p = 0; p < 4; p++) {
                    asm("fma.rn.f32x2 %0, %1, %2, %0;"
                        : "+l"(acc[q][0][p]) : "l"(e.x), "l"(zp[p]));
                    asm("fma.rn.f32x2 %0, %1, %2, %0;"
                        : "+l"(acc[q][1][p]) : "l"(e.y), "l"(zp[p]));
                }
            }
        }

        // fold: v = (zn - 2*dot) + en; k ascending within thread (q, then s)
        const int kbase = kt * BK;
        #pragma unroll
        for (int q = 0; q < 4; q++) {
            #pragma unroll
            for (int s = 0; s < 2; s++) {
                int k = kbase + 2 * (tck + 8 * q) + s;
                float en = __ldg(g_enorm + k);
                #pragma unroll
                for (int p = 0; p < 4; p++) {
                    unsigned long long a = acc[q][s][p];
                    float d0 = __uint_as_float((unsigned int)(a & 0xffffffffull));
                    float d1 = __uint_as_float((unsigned int)(a >> 32));
                    float v0 = __fadd_rn(__fsub_rn(zn[2 * p],     __fmul_rn(2.0f, d0)), en);
                    float v1 = __fadd_rn(__fsub_rn(zn[2 * p + 1], __fmul_rn(2.0f, d1)), en);
                    if (v0 < minval[2 * p])     { minval[2 * p]     = v0; minidx[2 * p]     = k; }
                    if (v1 < minval[2 * p + 1]) { minval[2 * p + 1] = v1; minidx[2 * p + 1] = k; }
                }
            }
        }
    }

    __syncthreads();   // done with smem -> safe to alias reduction buffers
    #pragma unroll
    for (int i = 0; i < 8; i++) {
        red_val[(m0 + i) * 8 + tck] = minval[i];
        red_idx[(m0 + i) * 8 + tck] = minidx[i];
    }
    __syncthreads();

    {   // one thread per point row; lowest index wins ties
        float bv = red_val[tid * 8];
        int   bi = red_idx[tid * 8];
        #pragma unroll
        for (int t = 1; t < 8; t++) {
            float v  = red_val[tid * 8 + t];
            int   id = red_idx[tid * 8 + t];
            if (v < bv || (v == bv && id < bi)) { bv = v; bi = id; }
        }
        g_idx[P0 + tid] = bi;
    }
}

// ---------------------------------------------------------------------------
// Output: one thread per POINT (owns all 64 channels). 1 idx load + 16 float4
// codebook reads per 64 outputs; x/o coalesced per fixed c; loss via shuffle.
// ---------------------------------------------------------------------------
__global__ void output_kernel(const float* __restrict__ x,
                              const float* __restrict__ emb,
                              float* __restrict__ out, int out_size) {
    int n  = blockIdx.x * 128 + threadIdx.x;       // n < N_PTS
    int b  = n >> 12;
    int hw = n & 4095;
    int idx = g_idx[n];
    if ((OFF_IDX + n) < out_size) out[OFF_IDX + n] = (float)idx;

    const float4* erow = reinterpret_cast<const float4*>(emb + (size_t)idx * C_DIM);
    const float* xb = x   + (size_t)b * C_DIM * HW + hw;
    float*       ob = out + (size_t)b * C_DIM * HW + hw;

    float s = 0.f;
    #pragma unroll
    for (int cq = 0; cq < 16; cq++) {
        float4 e4 = __ldg(erow + cq);
        float e[4] = { e4.x, e4.y, e4.z, e4.w };
        #pragma unroll
        for (int u = 0; u < 4; u++) {
            int c = cq * 4 + u;
            float xv = xb[(size_t)c * HW];
            float t  = __fsub_rn(e[u], xv);
            ob[(size_t)c * HW] = __fadd_rn(xv, t);
            s = fmaf(t, t, s);
        }
    }
    #pragma unroll
    for (int off = 16; off > 0; off >>= 1)
        s += __shfl_down_sync(0xffffffffu, s, off);
    if ((threadIdx.x & 31) == 0) g_partial[n >> 5] = s;
}

// ---------------------------------------------------------------------------
// Final loss reduction: loss = m + 0.25*m
// ---------------------------------------------------------------------------
__global__ void loss_kernel(float* __restrict__ out, int out_size) {
    __shared__ float red[256];
    float s = 0.f;
    for (int i = threadIdx.x; i < NPART; i += 256) s += g_partial[i];
    red[threadIdx.x] = s;
    __syncthreads();
    #pragma unroll
    for (int t = 128; t > 0; t >>= 1) {
        if (threadIdx.x < t) red[threadIdx.x] += red[threadIdx.x + t];
        __syncthreads();
    }
    if (threadIdx.x == 0 && OFF_LOSS < out_size) {
        float m = red[0] / (float)O_ELEMS;
        out[OFF_LOSS] = __fadd_rn(m, __fmul_rn(0.25f, m));
    }
}

// ---------------------------------------------------------------------------
extern "C" void kernel_launch(void* const* d_in, const int* in_sizes, int n_in,
                              void* d_out, int out_size) {
    const float* p0 = (const float*)d_in[0];
    const float* p1 = (const float*)d_in[1];
    const float* x;
    const float* emb;
    if (in_sizes[0] == K_CODES * C_DIM) { emb = p0; x = p1; }
    else                                { x = p0; emb = p1; }
    float* out = (float*)d_out;

    cudaFuncSetAttribute(argmin_kernel,
                         cudaFuncAttributeMaxDynamicSharedMemorySize, ARG_SMEM);

    enorm_kernel<<<K_CODES / 8, 256>>>(emb);
    znorm_kernel<<<N_PTS / 32, 256>>>(x);
    argmin_kernel<<<N_PTS / BM, TH, ARG_SMEM>>>(x, emb);
    output_kernel<<<N_PTS / 128, 128>>>(x, emb, out, out_size);
    loss_kernel<<<1, 256>>>(out, out_size);
}